// round 1
// baseline (speedup 1.0000x reference)
#include <cuda_runtime.h>
#include <math.h>

#define N_NODES 100000
#define N_EDGES 3200000
#define F_IN    128
#define DIM     10
#define NB      1000
#define RS      16      // padded row stride for 10-dim vectors (64B rows)

// ---- scratch (no allocations allowed; __device__ globals) ----
__device__ float d_cnt[N_NODES];          // in-degree per node
__device__ float d_p1[N_NODES * RS];      // x @ W1a  (self part, layer 1)
__device__ float d_q1[N_NODES * RS];      // x @ W1b  (neighbor-projected, layer 1)
__device__ float d_ag1[N_NODES * RS];     // segment_sum(q1[src], dst)
__device__ float d_p2[N_NODES * RS];      // h @ W2a
__device__ float d_q2[N_NODES * RS];      // h @ W2b
__device__ float d_ag2[N_NODES * RS];     // segment_sum(q2[src], dst)
__device__ float d_pool[NB];              // per-graph sum of h2@Wfc
__device__ float d_cntB[NB];              // nodes per graph

// ---------------------------------------------------------------------------
// K0: zero the accumulators
// ---------------------------------------------------------------------------
__global__ void k_zero() {
    int i = blockIdx.x * blockDim.x + threadIdx.x;
    if (i < N_NODES * RS) { d_ag1[i] = 0.0f; d_ag2[i] = 0.0f; }
    if (i < N_NODES) d_cnt[i] = 0.0f;
    if (i < NB) { d_pool[i] = 0.0f; d_cntB[i] = 0.0f; }
}

// ---------------------------------------------------------------------------
// K1: in-degree counts
// ---------------------------------------------------------------------------
__global__ void k_deg(const int* __restrict__ dst) {
    int e = blockIdx.x * blockDim.x + threadIdx.x;
    if (e < N_EDGES) atomicAdd(&d_cnt[dst[e]], 1.0f);
}

// ---------------------------------------------------------------------------
// K2: layer-1 projection.  p1 = x@W1[0:128], q1 = x@W1[128:256]
// One thread per node, block = 128 nodes; x tile staged in shared in 32-col
// chunks; W (re-packed [f][20]) staged in shared, loaded as uniform float4s.
// ---------------------------------------------------------------------------
__global__ void __launch_bounds__(128) k_proj1(const float* __restrict__ x,
                                               const float* __restrict__ W1) {
    __shared__ float Ws[F_IN * 20];     // Ws[f*20+o]: o<10 -> W1a, o>=10 -> W1b
    __shared__ float xs[128 * 33];      // 128 nodes x 32 cols, pad 33

    const int t = threadIdx.x;
    for (int i = t; i < F_IN * 20; i += 128) {
        int f = i / 20, o = i % 20;
        Ws[i] = (o < 10) ? W1[f * 10 + o] : W1[(F_IN + f) * 10 + (o - 10)];
    }

    const int nodeBase = blockIdx.x * 128;
    float acc[20];
#pragma unroll
    for (int o = 0; o < 20; o++) acc[o] = 0.0f;

    for (int c = 0; c < 4; c++) {       // 4 chunks of 32 features
        __syncthreads();
        // cooperative coalesced load of 128x32 tile (1024 float4, 8 per thread)
#pragma unroll
        for (int k = 0; k < 8; k++) {
            int idx = t + k * 128;
            int row = idx >> 3;         // 8 float4 per row-chunk
            int c4  = idx & 7;
            float4 v = make_float4(0.f, 0.f, 0.f, 0.f);
            int node = nodeBase + row;
            if (node < N_NODES)
                v = *(const float4*)(x + (size_t)node * F_IN + c * 32 + c4 * 4);
            float* xr = &xs[row * 33 + c4 * 4];
            xr[0] = v.x; xr[1] = v.y; xr[2] = v.z; xr[3] = v.w;
        }
        __syncthreads();
#pragma unroll
        for (int f = 0; f < 32; f++) {
            float xv = xs[t * 33 + f];
            const float* wr = &Ws[(c * 32 + f) * 20];
            float4 w0 = *(const float4*)(wr + 0);
            float4 w1 = *(const float4*)(wr + 4);
            float4 w2 = *(const float4*)(wr + 8);
            float4 w3 = *(const float4*)(wr + 12);
            float4 w4 = *(const float4*)(wr + 16);
            acc[0]  += xv * w0.x; acc[1]  += xv * w0.y; acc[2]  += xv * w0.z; acc[3]  += xv * w0.w;
            acc[4]  += xv * w1.x; acc[5]  += xv * w1.y; acc[6]  += xv * w1.z; acc[7]  += xv * w1.w;
            acc[8]  += xv * w2.x; acc[9]  += xv * w2.y; acc[10] += xv * w2.z; acc[11] += xv * w2.w;
            acc[12] += xv * w3.x; acc[13] += xv * w3.y; acc[14] += xv * w3.z; acc[15] += xv * w3.w;
            acc[16] += xv * w4.x; acc[17] += xv * w4.y; acc[18] += xv * w4.z; acc[19] += xv * w4.w;
        }
    }

    const int node = nodeBase + t;
    if (node < N_NODES) {
#pragma unroll
        for (int o = 0; o < 10; o++) {
            d_p1[(size_t)node * RS + o] = acc[o];
            d_q1[(size_t)node * RS + o] = acc[10 + o];
        }
    }
}

// ---------------------------------------------------------------------------
// K3/K5: edge aggregation.  ag[dst] += q[src]  (10 floats via v4/v4/v2 red)
// layer flag selects q1->ag1 or q2->ag2.
// ---------------------------------------------------------------------------
__device__ __forceinline__ void red4(float* p, float4 v) {
    asm volatile("red.global.add.v4.f32 [%0], {%1,%2,%3,%4};"
                 :: "l"(p), "f"(v.x), "f"(v.y), "f"(v.z), "f"(v.w) : "memory");
}
__device__ __forceinline__ void red2(float* p, float2 v) {
    asm volatile("red.global.add.v2.f32 [%0], {%1,%2};"
                 :: "l"(p), "f"(v.x), "f"(v.y) : "memory");
}

__global__ void __launch_bounds__(256) k_edge(const int* __restrict__ src,
                                              const int* __restrict__ dst,
                                              int layer) {
    int e = blockIdx.x * blockDim.x + threadIdx.x;
    if (e >= N_EDGES) return;
    const float* q = layer ? d_q2 : d_q1;
    float*      ag = layer ? d_ag2 : d_ag1;
    int s = src[e], d = dst[e];
    const float* qr = q + (size_t)s * RS;
    float4 a = *(const float4*)(qr + 0);
    float4 b = *(const float4*)(qr + 4);
    float2 c = *(const float2*)(qr + 8);
    float* dr = ag + (size_t)d * RS;
    red4(dr + 0, a);
    red4(dr + 4, b);
    red2(dr + 8, c);
}

// ---------------------------------------------------------------------------
// K4: h = relu(p1 + ag1/max(cnt,1));  p2 = h@W2a, q2 = h@W2b
// ---------------------------------------------------------------------------
__global__ void __launch_bounds__(256) k_layer2(const float* __restrict__ W2) {
    __shared__ float Ws[10 * 20];   // Ws[j*20+o]: o<10 -> W2a, o>=10 -> W2b
    int t = threadIdx.x;
    if (t < 200) {
        int j = t / 20, o = t % 20;
        Ws[t] = (o < 10) ? W2[j * 10 + o] : W2[(10 + j) * 10 + (o - 10)];
    }
    __syncthreads();

    int node = blockIdx.x * blockDim.x + t;
    if (node >= N_NODES) return;
    float inv = 1.0f / fmaxf(d_cnt[node], 1.0f);

    float h[10];
    const float* p = d_p1 + (size_t)node * RS;
    const float* a = d_ag1 + (size_t)node * RS;
#pragma unroll
    for (int j = 0; j < 10; j++)
        h[j] = fmaxf(p[j] + a[j] * inv, 0.0f);

    float acc[20];
#pragma unroll
    for (int o = 0; o < 20; o++) acc[o] = 0.0f;
#pragma unroll
    for (int j = 0; j < 10; j++) {
        float hv = h[j];
#pragma unroll
        for (int o = 0; o < 20; o++) acc[o] += hv * Ws[j * 20 + o];
    }
#pragma unroll
    for (int o = 0; o < 10; o++) {
        d_p2[(size_t)node * RS + o] = acc[o];
        d_q2[(size_t)node * RS + o] = acc[10 + o];
    }
}

// ---------------------------------------------------------------------------
// K6: h2 = p2 + ag2/max(cnt,1);  s = h2@Wfc;  pool[batch] += s; cntB[batch]++
// ---------------------------------------------------------------------------
__global__ void __launch_bounds__(256) k_pool(const int* __restrict__ batch,
                                              const float* __restrict__ Wfc) {
    int node = blockIdx.x * blockDim.x + threadIdx.x;
    if (node >= N_NODES) return;
    float inv = 1.0f / fmaxf(d_cnt[node], 1.0f);
    const float* p = d_p2 + (size_t)node * RS;
    const float* a = d_ag2 + (size_t)node * RS;
    float s = 0.0f;
#pragma unroll
    for (int j = 0; j < 10; j++)
        s += (p[j] + a[j] * inv) * __ldg(&Wfc[j]);
    int b = batch[node];
    atomicAdd(&d_pool[b], s);
    atomicAdd(&d_cntB[b], 1.0f);
}

// ---------------------------------------------------------------------------
// K7: out[b] = sigmoid(pool[b] / max(cntB[b],1))
// ---------------------------------------------------------------------------
__global__ void k_out(float* __restrict__ out) {
    int b = blockIdx.x * blockDim.x + threadIdx.x;
    if (b < NB) {
        float g = d_pool[b] / fmaxf(d_cntB[b], 1.0f);
        out[b] = 1.0f / (1.0f + expf(-g));
    }
}

// ---------------------------------------------------------------------------
extern "C" void kernel_launch(void* const* d_in, const int* in_sizes, int n_in,
                              void* d_out, int out_size) {
    const float* x   = (const float*)d_in[0];
    const int*   ei  = (const int*)d_in[1];
    const int*   bat = (const int*)d_in[2];
    const float* W1  = (const float*)d_in[3];
    const float* W2  = (const float*)d_in[4];
    const float* Wfc = (const float*)d_in[5];
    float* out = (float*)d_out;

    const int* src = ei;
    const int* dst = ei + N_EDGES;

    k_zero<<<(N_NODES * RS + 255) / 256, 256>>>();
    k_deg<<<(N_EDGES + 255) / 256, 256>>>(dst);
    k_proj1<<<(N_NODES + 127) / 128, 128>>>(x, W1);
    k_edge<<<(N_EDGES + 255) / 256, 256>>>(src, dst, 0);
    k_layer2<<<(N_NODES + 255) / 256, 256>>>(W2);
    k_edge<<<(N_EDGES + 255) / 256, 256>>>(src, dst, 1);
    k_pool<<<(N_NODES + 255) / 256, 256>>>(bat, Wfc);
    k_out<<<(NB + 255) / 256, 256>>>(out);
}